// round 1
// baseline (speedup 1.0000x reference)
#include <cuda_runtime.h>

#define NA 256
#define NB 512
#define CMAX 0.05f
#define NITERS 300
#define BISECT 60
#define PITERS 30

// Scratch for Q = A^T A per batch: 512 * 256 * 256 floats = 134 MB
__device__ float g_Q[(size_t)NB * NA * NA];

// ---------------------------------------------------------------------------
// Kernel 1: batched Q = A^T A.  Grid (4,4,512) tiles of 64x64, 256 threads.
// C[i][j] = sum_k A[k][i] * A[k][j]
// ---------------------------------------------------------------------------
__global__ __launch_bounds__(256) void qbuild_kernel(const float* __restrict__ A) {
    __shared__ float As[32][64];
    __shared__ float Bs[32][64];
    const int b  = blockIdx.z;
    const int i0 = blockIdx.x * 64;
    const int j0 = blockIdx.y * 64;
    const float* Ab = A + (size_t)b * NA * NA;
    float*       Qb = g_Q + (size_t)b * NA * NA;
    const int t  = threadIdx.x;
    const int ty = t >> 4;    // 0..15
    const int tx = t & 15;    // 0..15

    float acc[4][4];
#pragma unroll
    for (int r = 0; r < 4; r++)
#pragma unroll
        for (int s = 0; s < 4; s++) acc[r][s] = 0.0f;

    for (int k0 = 0; k0 < NA; k0 += 32) {
        __syncthreads();
#pragma unroll
        for (int r = 0; r < 8; r++) {
            int idx = t + 256 * r;
            int kk = idx >> 6, c = idx & 63;
            As[kk][c] = Ab[(size_t)(k0 + kk) * NA + i0 + c];
            Bs[kk][c] = Ab[(size_t)(k0 + kk) * NA + j0 + c];
        }
        __syncthreads();
#pragma unroll
        for (int kk = 0; kk < 32; kk++) {
            float4 a4 = *(const float4*)&As[kk][ty * 4];
            float4 b4 = *(const float4*)&Bs[kk][tx * 4];
            float av[4] = {a4.x, a4.y, a4.z, a4.w};
            float bv[4] = {b4.x, b4.y, b4.z, b4.w};
#pragma unroll
            for (int r = 0; r < 4; r++)
#pragma unroll
                for (int s = 0; s < 4; s++)
                    acc[r][s] = fmaf(av[r], bv[s], acc[r][s]);
        }
    }
#pragma unroll
    for (int r = 0; r < 4; r++) {
        float4 o = make_float4(acc[r][0], acc[r][1], acc[r][2], acc[r][3]);
        *(float4*)&Qb[(size_t)(i0 + ty * 4 + r) * NA + j0 + tx * 4] = o;
    }
}

// ---------------------------------------------------------------------------
// Matvec: out partials in red[4*NA]; out_i = sum_j Q[j][i] * y[j]
// (Q symmetric, column access == row access, coalesced across threads)
// Thread layout: g = t>>6 handles j in [64g, 64g+64); t4 = t&63 handles
// outputs 4*t4 .. 4*t4+3 via float4 loads.
// ---------------------------------------------------------------------------
__device__ __forceinline__ void matvec256(const float4* __restrict__ Q4,
                                          const float* __restrict__ yv,
                                          float* __restrict__ red,
                                          int g, int t4) {
    float4 acc = make_float4(0.0f, 0.0f, 0.0f, 0.0f);
    const float4* qp = Q4 + (size_t)(g * 64) * 64 + t4;
    const float*  yp = yv + g * 64;
#pragma unroll 8
    for (int jj = 0; jj < 64; jj++) {
        float y = yp[jj];
        float4 q = qp[(size_t)jj * 64];
        acc.x = fmaf(q.x, y, acc.x);
        acc.y = fmaf(q.y, y, acc.y);
        acc.z = fmaf(q.z, y, acc.z);
        acc.w = fmaf(q.w, y, acc.w);
    }
    ((float4*)(red + g * NA))[t4] = acc;
}

__device__ __forceinline__ float warp_sum(float v) {
#pragma unroll
    for (int off = 16; off; off >>= 1)
        v += __shfl_xor_sync(0xffffffffu, v, off);
    return v;
}

// ---------------------------------------------------------------------------
// Kernel 2: per-batch solver. 1 CTA per batch, 256 threads.
// ---------------------------------------------------------------------------
__global__ __launch_bounds__(256) void solver_kernel(float* __restrict__ out) {
    __shared__ float ys[NA];       // current y (FISTA) / u (power iter)
    __shared__ float ws[NA];       // current w
    __shared__ float vs[NA];       // scratch: z = Q*y, then v = y - step*g
    __shared__ float red[4 * NA];  // matvec partials
    __shared__ float scal[2];      // [0]=step, [1]=tau

    const int b  = blockIdx.x;
    const int t  = threadIdx.x;
    const int g  = t >> 6;
    const int t4 = t & 63;
    const float4* Q4 = (const float4*)(g_Q + (size_t)b * NA * NA);

    // ---------------- power iteration for lambda_max ----------------
    ys[t] = 0.0625f;  // 1/sqrt(256)
    __syncthreads();
    for (int it = 0; it < PITERS; it++) {
        matvec256(Q4, ys, red, g, t4);
        __syncthreads();
        vs[t] = red[t] + red[NA + t] + red[2 * NA + t] + red[3 * NA + t];
        __syncthreads();
        if (t < 32) {
            float zr[8];
            float ss = 0.0f;
#pragma unroll
            for (int k = 0; k < 8; k++) { zr[k] = vs[t + 32 * k]; ss = fmaf(zr[k], zr[k], ss); }
            ss = warp_sum(ss);
            float inv = 1.0f / (sqrtf(ss) + 1e-12f);
#pragma unroll
            for (int k = 0; k < 8; k++) ys[t + 32 * k] = zr[k] * inv;
        }
        __syncthreads();
    }
    // lmax = u^T Q u ; step = 1/(2*lmax + 1e-12)
    matvec256(Q4, ys, red, g, t4);
    __syncthreads();
    vs[t] = red[t] + red[NA + t] + red[2 * NA + t] + red[3 * NA + t];
    __syncthreads();
    if (t < 32) {
        float ss = 0.0f;
#pragma unroll
        for (int k = 0; k < 8; k++) ss = fmaf(ys[t + 32 * k], vs[t + 32 * k], ss);
        ss = warp_sum(ss);
        if (t == 0) scal[0] = 1.0f / (2.0f * ss + 1e-12f);
    }
    __syncthreads();
    const float step = scal[0];

    // ---------------- FISTA ----------------
    // w0 = project(1/n * ones) == 1/n exactly (feasible point, tau = 0 exact)
    ws[t] = 1.0f / 256.0f;
    ys[t] = 1.0f / 256.0f;
    float tf = 1.0f;
    __syncthreads();

    for (int it = 0; it < NITERS; it++) {
        matvec256(Q4, ys, red, g, t4);
        __syncthreads();
        {
            float zz = red[t] + red[NA + t] + red[2 * NA + t] + red[3 * NA + t];
            vs[t] = ys[t] - step * (2.0f * zz);
        }
        __syncthreads();

        // --- projection onto {sum = 1, -c <= w <= c}, warp 0 only ---
        if (t < 32) {
            float vr[8];
#pragma unroll
            for (int k = 0; k < 8; k++) vr[k] = vs[t + 32 * k];
            float mn = vr[0], mx = vr[0];
#pragma unroll
            for (int k = 1; k < 8; k++) { mn = fminf(mn, vr[k]); mx = fmaxf(mx, vr[k]); }
#pragma unroll
            for (int off = 16; off; off >>= 1) {
                mn = fminf(mn, __shfl_xor_sync(0xffffffffu, mn, off));
                mx = fmaxf(mx, __shfl_xor_sync(0xffffffffu, mx, off));
            }
            float lo = mn - CMAX;
            float hi = mx + CMAX;
            for (int bi = 0; bi < BISECT; bi++) {
                float mid = 0.5f * (lo + hi);
                float c0 = fminf(fmaxf(vr[0] - mid, -CMAX), CMAX);
                float c1 = fminf(fmaxf(vr[1] - mid, -CMAX), CMAX);
                float c2 = fminf(fmaxf(vr[2] - mid, -CMAX), CMAX);
                float c3 = fminf(fmaxf(vr[3] - mid, -CMAX), CMAX);
                float c4 = fminf(fmaxf(vr[4] - mid, -CMAX), CMAX);
                float c5 = fminf(fmaxf(vr[5] - mid, -CMAX), CMAX);
                float c6 = fminf(fmaxf(vr[6] - mid, -CMAX), CMAX);
                float c7 = fminf(fmaxf(vr[7] - mid, -CMAX), CMAX);
                float s = ((c0 + c1) + (c2 + c3)) + ((c4 + c5) + (c6 + c7));
                s = warp_sum(s);
                bool p = s > 1.0f;
                lo = p ? mid : lo;
                hi = p ? hi : mid;
            }
            float tau0 = 0.5f * (lo + hi);
            float sv = 0.0f, cnt = 0.0f, dk = 0.0f;
#pragma unroll
            for (int k = 0; k < 8; k++) {
                float z = vr[k] - tau0;
                bool in = fabsf(z) < CMAX;
                if (in) { sv += vr[k]; cnt += 1.0f; }
                else    { dk += (z >= CMAX) ? 1.0f : -1.0f; }  // k_hi - k_lo
            }
            sv  = warp_sum(sv);
            cnt = warp_sum(cnt);
            dk  = warp_sum(dk);
            float denom = fmaxf(cnt, 1.0f);
            float tau = (sv + CMAX * dk - 1.0f) / denom;
            if (t == 0) scal[1] = tau;
        }
        __syncthreads();

        // --- momentum update ---
        {
            float tau = scal[1];
            float wn = fminf(fmaxf(vs[t] - tau, -CMAX), CMAX);
            float tn = 0.5f * (1.0f + sqrtf(1.0f + 4.0f * tf * tf));
            float yn = wn + ((tf - 1.0f) / tn) * (wn - ws[t]);
            ws[t] = wn;
            ys[t] = yn;
            tf = tn;
        }
        __syncthreads();
    }

    out[(size_t)b * NA + t] = ws[t];
}

// ---------------------------------------------------------------------------
extern "C" void kernel_launch(void* const* d_in, const int* in_sizes, int n_in,
                              void* d_out, int out_size) {
    (void)in_sizes; (void)n_in; (void)out_size;
    const float* A = (const float*)d_in[0];
    float* out = (float*)d_out;

    qbuild_kernel<<<dim3(4, 4, NB), 256>>>(A);
    solver_kernel<<<NB, 256>>>(out);
}

// round 3
// speedup vs baseline: 1.2692x; 1.2692x over previous
#include <cuda_runtime.h>

#define NA 256
#define NB 512
#define CMAX 0.05f
#define NITERS 300
#define PITERS 30
#define TRIROUNDS 16   // quartile search: 2 bits/round -> 32 bits of tau

// Upper-triangular Q blocks, fp32: 512 batches * 10 blocks * 64*64 floats = 82 MB (fits L2)
__device__ float g_Qs[(size_t)NB * 10 * 4096];

__constant__ int c_gi[10] = {0,0,0,0,1,1,1,2,2,3};
__constant__ int c_gj[10] = {0,1,2,3,1,2,3,2,3,3};

// ---------------------------------------------------------------------------
// Kernel 1: batched Q = A^T A, upper-triangular 64x64 tiles only.
// Grid (10,1,512), 256 threads. C[i][j] = sum_k A[k][i]*A[k][j]
// ---------------------------------------------------------------------------
__global__ __launch_bounds__(256) void qbuild_kernel(const float* __restrict__ A) {
    __shared__ float As[32][64];
    __shared__ float Bs[32][64];
    const int blk = blockIdx.x;
    const int b   = blockIdx.z;
    const int i0  = c_gi[blk] * 64;
    const int j0  = c_gj[blk] * 64;
    const float* Ab = A + (size_t)b * NA * NA;
    float*       Qb = g_Qs + ((size_t)b * 10 + blk) * 4096;
    const int t  = threadIdx.x;
    const int ty = t >> 4;
    const int tx = t & 15;

    float acc[4][4];
#pragma unroll
    for (int r = 0; r < 4; r++)
#pragma unroll
        for (int s = 0; s < 4; s++) acc[r][s] = 0.0f;

    for (int k0 = 0; k0 < NA; k0 += 32) {
        __syncthreads();
#pragma unroll
        for (int r = 0; r < 8; r++) {
            int idx = t + 256 * r;
            int kk = idx >> 6, c = idx & 63;
            As[kk][c] = Ab[(size_t)(k0 + kk) * NA + i0 + c];
            Bs[kk][c] = Ab[(size_t)(k0 + kk) * NA + j0 + c];
        }
        __syncthreads();
#pragma unroll
        for (int kk = 0; kk < 32; kk++) {
            float4 a4 = *(const float4*)&As[kk][ty * 4];
            float4 b4 = *(const float4*)&Bs[kk][tx * 4];
            float av[4] = {a4.x, a4.y, a4.z, a4.w};
            float bv[4] = {b4.x, b4.y, b4.z, b4.w};
#pragma unroll
            for (int r = 0; r < 4; r++)
#pragma unroll
                for (int s = 0; s < 4; s++)
                    acc[r][s] = fmaf(av[r], bv[s], acc[r][s]);
        }
    }
    // block stored row-major [64][64]: row = i-local, col = j-local
#pragma unroll
    for (int r = 0; r < 4; r++) {
        float4 o = make_float4(acc[r][0], acc[r][1], acc[r][2], acc[r][3]);
        *(float4*)&Qb[(ty * 4 + r) * 64 + tx * 4] = o;
    }
}

// ---------------------------------------------------------------------------
// Symmetric matvec using only upper-triangular blocks.
// Thread (ty=t>>4, tx=t&15): per block handles rows {ty+16k}, cols 4tx..4tx+3.
// Column path: cacc[gj][0..3]  (out[gj] += B^T y[gi], i.e. standard)
// Row path:    racc[gi][k]     (out[gi] += B  y[gj], off-diag only)
// Returns z[t] = (Q y)[t].  Requires rowsum[] zeroed before call; zeroes it
// again at the end (caller must have >=1 __syncthreads between calls).
// ---------------------------------------------------------------------------
__device__ __forceinline__ float symv(const float* __restrict__ Qb,
                                      const float* __restrict__ y,
                                      float* __restrict__ red,
                                      float* __restrict__ rowsum,
                                      int t, int ty, int tx) {
    constexpr int GI[10] = {0,0,0,0,1,1,1,2,2,3};
    constexpr int GJ[10] = {0,1,2,3,1,2,3,2,3,3};
    float cacc[4][4];
    float racc[3][4];
#pragma unroll
    for (int s = 0; s < 4; s++)
#pragma unroll
        for (int c = 0; c < 4; c++) cacc[s][c] = 0.0f;
#pragma unroll
    for (int s = 0; s < 3; s++)
#pragma unroll
        for (int k = 0; k < 4; k++) racc[s][k] = 0.0f;

#pragma unroll
    for (int blk = 0; blk < 10; blk++) {
        const int gi = GI[blk];
        const int gj = GJ[blk];
        const float4* B4 = (const float4*)(Qb + blk * 4096);
        float4 yj = ((const float4*)(y + gj * 64))[tx];
#pragma unroll
        for (int k = 0; k < 4; k++) {
            int r = ty + 16 * k;
            float4 q = B4[r * 16 + tx];
            float yi = y[gi * 64 + r];
            cacc[gj][0] = fmaf(q.x, yi, cacc[gj][0]);
            cacc[gj][1] = fmaf(q.y, yi, cacc[gj][1]);
            cacc[gj][2] = fmaf(q.z, yi, cacc[gj][2]);
            cacc[gj][3] = fmaf(q.w, yi, cacc[gj][3]);
            if (gi != gj) {
                float d = q.x * yj.x;
                d = fmaf(q.y, yj.y, d);
                d = fmaf(q.z, yj.z, d);
                d = fmaf(q.w, yj.w, d);
                racc[gi][k] += d;
            }
        }
    }

    // column partials -> red[ty][seg*64 + col]
#pragma unroll
    for (int s = 0; s < 4; s++)
        ((float4*)(red + ty * NA + s * 64))[tx] =
            make_float4(cacc[s][0], cacc[s][1], cacc[s][2], cacc[s][3]);

    // row partials: reduce across the 16 tx lanes (half-warp)
#pragma unroll
    for (int gi = 0; gi < 3; gi++)
#pragma unroll
        for (int k = 0; k < 4; k++) {
            float v = racc[gi][k];
            v += __shfl_xor_sync(0xffffffffu, v, 1);
            v += __shfl_xor_sync(0xffffffffu, v, 2);
            v += __shfl_xor_sync(0xffffffffu, v, 4);
            v += __shfl_xor_sync(0xffffffffu, v, 8);
            if (tx == 0) rowsum[gi * 64 + ty + 16 * k] += v;
        }
    __syncthreads();

    float z = rowsum[t];
#pragma unroll
    for (int q = 0; q < 16; q++) z += red[q * NA + t];
    rowsum[t] = 0.0f;   // reset own element for next call (safe: own slot)
    return z;
}

__device__ __forceinline__ float warp_sum(float v) {
#pragma unroll
    for (int off = 16; off; off >>= 1)
        v += __shfl_xor_sync(0xffffffffu, v, off);
    return v;
}

__device__ __forceinline__ void warp_sum3(float& a, float& b, float& c) {
#pragma unroll
    for (int off = 16; off; off >>= 1) {
        a += __shfl_xor_sync(0xffffffffu, a, off);
        b += __shfl_xor_sync(0xffffffffu, b, off);
        c += __shfl_xor_sync(0xffffffffu, c, off);
    }
}

__device__ __forceinline__ float clipc(float z) {
    return fminf(fmaxf(z, -CMAX), CMAX);
}

// ---------------------------------------------------------------------------
// Kernel 2: per-batch solver. 1 CTA per batch, 256 threads.
// ---------------------------------------------------------------------------
__global__ __launch_bounds__(256) void solver_kernel(float* __restrict__ out) {
    __shared__ float ys[NA];
    __shared__ float ws[NA];
    __shared__ float vs[NA];
    __shared__ float rowsum[NA];
    __shared__ float red[16 * NA];
    __shared__ float scal[2];

    const int b  = blockIdx.x;
    const int t  = threadIdx.x;
    const int ty = t >> 4;
    const int tx = t & 15;
    const float* Qb = g_Qs + (size_t)b * 10 * 4096;

    // ---------------- power iteration for lambda_max ----------------
    ys[t] = 0.0625f;       // 1/sqrt(256)
    rowsum[t] = 0.0f;
    __syncthreads();
    for (int it = 0; it < PITERS; it++) {
        float z = symv(Qb, ys, red, rowsum, t, ty, tx);
        vs[t] = z;
        __syncthreads();
        if (t < 32) {
            float zr[8];
            float ss = 0.0f;
#pragma unroll
            for (int k = 0; k < 8; k++) { zr[k] = vs[t + 32 * k]; ss = fmaf(zr[k], zr[k], ss); }
            ss = warp_sum(ss);
            float inv = 1.0f / (sqrtf(ss) + 1e-12f);
#pragma unroll
            for (int k = 0; k < 8; k++) ys[t + 32 * k] = zr[k] * inv;
        }
        __syncthreads();
    }
    {
        float z = symv(Qb, ys, red, rowsum, t, ty, tx);
        vs[t] = z;
        __syncthreads();
        if (t < 32) {
            float ss = 0.0f;
#pragma unroll
            for (int k = 0; k < 8; k++) ss = fmaf(ys[t + 32 * k], vs[t + 32 * k], ss);
            ss = warp_sum(ss);
            if (t == 0) scal[0] = 1.0f / (2.0f * ss + 1e-12f);
        }
        __syncthreads();
    }
    const float step = scal[0];

    // ---------------- FISTA ----------------
    ws[t] = 1.0f / 256.0f;
    ys[t] = 1.0f / 256.0f;
    float tf = 1.0f;
    __syncthreads();

    for (int it = 0; it < NITERS; it++) {
        float z = symv(Qb, ys, red, rowsum, t, ty, tx);
        vs[t] = ys[t] - step * (2.0f * z);
        __syncthreads();

        // --- projection: 3-point quartile search on warp 0 ---
        if (t < 32) {
            float vr[8];
#pragma unroll
            for (int k = 0; k < 8; k++) vr[k] = vs[t + 32 * k];
            float mn = vr[0], mx = vr[0];
#pragma unroll
            for (int k = 1; k < 8; k++) { mn = fminf(mn, vr[k]); mx = fmaxf(mx, vr[k]); }
#pragma unroll
            for (int off = 16; off; off >>= 1) {
                mn = fminf(mn, __shfl_xor_sync(0xffffffffu, mn, off));
                mx = fmaxf(mx, __shfl_xor_sync(0xffffffffu, mx, off));
            }
            float lo = mn - CMAX;
            float hi = mx + CMAX;
            for (int r = 0; r < TRIROUNDS; r++) {
                float d  = hi - lo;
                float m1 = lo + 0.25f * d;
                float m2 = lo + 0.50f * d;
                float m3 = lo + 0.75f * d;
                float s1 = 0.0f, s2 = 0.0f, s3 = 0.0f;
#pragma unroll
                for (int k = 0; k < 8; k++) {
                    s1 += clipc(vr[k] - m1);
                    s2 += clipc(vr[k] - m2);
                    s3 += clipc(vr[k] - m3);
                }
                warp_sum3(s1, s2, s3);
                if (s2 > 1.0f) {
                    bool p3 = s3 > 1.0f;
                    lo = p3 ? m3 : m2;
                    hi = p3 ? hi : m3;
                } else {
                    bool p1 = s1 > 1.0f;
                    lo = p1 ? m1 : lo;
                    hi = p1 ? m2 : m1;
                }
            }
            float tau0 = 0.5f * (lo + hi);
            float sv = 0.0f, cnt = 0.0f, dk = 0.0f;
#pragma unroll
            for (int k = 0; k < 8; k++) {
                float zz = vr[k] - tau0;
                bool in = fabsf(zz) < CMAX;
                if (in) { sv += vr[k]; cnt += 1.0f; }
                else    { dk += (zz >= CMAX) ? 1.0f : -1.0f; }
            }
            warp_sum3(sv, cnt, dk);
            float denom = fmaxf(cnt, 1.0f);
            float tau = (sv + CMAX * dk - 1.0f) / denom;
            if (t == 0) scal[1] = tau;
        }
        __syncthreads();

        // --- momentum update ---
        {
            float tau = scal[1];
            float wn = clipc(vs[t] - tau);
            float tn = 0.5f * (1.0f + sqrtf(1.0f + 4.0f * tf * tf));
            float yn = wn + ((tf - 1.0f) / tn) * (wn - ws[t]);
            ws[t] = wn;
            ys[t] = yn;
            tf = tn;
        }
        __syncthreads();
    }

    out[(size_t)b * NA + t] = ws[t];
}

// ---------------------------------------------------------------------------
extern "C" void kernel_launch(void* const* d_in, const int* in_sizes, int n_in,
                              void* d_out, int out_size) {
    (void)in_sizes; (void)n_in; (void)out_size;
    const float* A = (const float*)d_in[0];
    float* out = (float*)d_out;

    qbuild_kernel<<<dim3(10, 1, NB), 256>>>(A);
    solver_kernel<<<NB, 256>>>(out);
}

// round 6
// speedup vs baseline: 1.6560x; 1.3047x over previous
#include <cuda_runtime.h>

#define NA 256
#define NB 512
#define CMAX 0.05f
#define NITERS 300
#define PITERS 30
#define TRIROUNDS 12   // quartile search: 2 bits/round -> 24 bits of tau

// Upper-triangular Q blocks, fp32: 512 batches * 10 blocks * 64*64 floats = 82 MB
__device__ float g_Qs[(size_t)NB * 10 * 4096];

__constant__ int c_gi[10] = {0,0,0,0,1,1,1,2,2,3};
__constant__ int c_gj[10] = {0,1,2,3,1,2,3,2,3,3};

// ---------------------------------------------------------------------------
// Kernel 1: batched Q = A^T A, upper-triangular 64x64 tiles only.
// Grid (10,1,512), 256 threads. C[i][j] = sum_k A[k][i]*A[k][j]
// ---------------------------------------------------------------------------
__global__ __launch_bounds__(256) void qbuild_kernel(const float* __restrict__ A) {
    __shared__ float As[32][64];
    __shared__ float Bs[32][64];
    const int blk = blockIdx.x;
    const int b   = blockIdx.z;
    const int i0  = c_gi[blk] * 64;
    const int j0  = c_gj[blk] * 64;
    const float* Ab = A + (size_t)b * NA * NA;
    float*       Qb = g_Qs + ((size_t)b * 10 + blk) * 4096;
    const int t  = threadIdx.x;
    const int ty = t >> 4;
    const int tx = t & 15;

    float acc[4][4];
#pragma unroll
    for (int r = 0; r < 4; r++)
#pragma unroll
        for (int s = 0; s < 4; s++) acc[r][s] = 0.0f;

    for (int k0 = 0; k0 < NA; k0 += 32) {
        __syncthreads();
#pragma unroll
        for (int r = 0; r < 8; r++) {
            int idx = t + 256 * r;
            int kk = idx >> 6, c = idx & 63;
            As[kk][c] = Ab[(size_t)(k0 + kk) * NA + i0 + c];
            Bs[kk][c] = Ab[(size_t)(k0 + kk) * NA + j0 + c];
        }
        __syncthreads();
#pragma unroll
        for (int kk = 0; kk < 32; kk++) {
            float4 a4 = *(const float4*)&As[kk][ty * 4];
            float4 b4 = *(const float4*)&Bs[kk][tx * 4];
            float av[4] = {a4.x, a4.y, a4.z, a4.w};
            float bv[4] = {b4.x, b4.y, b4.z, b4.w};
#pragma unroll
            for (int r = 0; r < 4; r++)
#pragma unroll
                for (int s = 0; s < 4; s++)
                    acc[r][s] = fmaf(av[r], bv[s], acc[r][s]);
        }
    }
#pragma unroll
    for (int r = 0; r < 4; r++) {
        float4 o = make_float4(acc[r][0], acc[r][1], acc[r][2], acc[r][3]);
        *(float4*)&Qb[(ty * 4 + r) * 64 + tx * 4] = o;
    }
}

// ---------------------------------------------------------------------------
// Symmetric matvec from SMEM-resident upper-tri Q.
// Thread (ty=t>>4, tx=t&15): per block handles rows {ty+16k}, cols 4tx..4tx+3.
// ---------------------------------------------------------------------------
__device__ __forceinline__ float symv(const float* __restrict__ Qb,
                                      const float* __restrict__ y,
                                      float* __restrict__ red,
                                      float* __restrict__ rowsum,
                                      int t, int ty, int tx) {
    constexpr int GI[10] = {0,0,0,0,1,1,1,2,2,3};
    constexpr int GJ[10] = {0,1,2,3,1,2,3,2,3,3};
    float cacc[4][4];
    float racc[3][4];
#pragma unroll
    for (int s = 0; s < 4; s++)
#pragma unroll
        for (int c = 0; c < 4; c++) cacc[s][c] = 0.0f;
#pragma unroll
    for (int s = 0; s < 3; s++)
#pragma unroll
        for (int k = 0; k < 4; k++) racc[s][k] = 0.0f;

#pragma unroll
    for (int blk = 0; blk < 10; blk++) {
        const int gi = GI[blk];
        const int gj = GJ[blk];
        const float4* B4 = (const float4*)(Qb + blk * 4096);
        float4 yj = ((const float4*)(y + gj * 64))[tx];
#pragma unroll
        for (int k = 0; k < 4; k++) {
            int r = ty + 16 * k;
            float4 q = B4[r * 16 + tx];
            float yi = y[gi * 64 + r];
            cacc[gj][0] = fmaf(q.x, yi, cacc[gj][0]);
            cacc[gj][1] = fmaf(q.y, yi, cacc[gj][1]);
            cacc[gj][2] = fmaf(q.z, yi, cacc[gj][2]);
            cacc[gj][3] = fmaf(q.w, yi, cacc[gj][3]);
            if (gi != gj) {
                float d = q.x * yj.x;
                d = fmaf(q.y, yj.y, d);
                d = fmaf(q.z, yj.z, d);
                d = fmaf(q.w, yj.w, d);
                racc[gi][k] += d;
            }
        }
    }

#pragma unroll
    for (int s = 0; s < 4; s++)
        ((float4*)(red + ty * NA + s * 64))[tx] =
            make_float4(cacc[s][0], cacc[s][1], cacc[s][2], cacc[s][3]);

#pragma unroll
    for (int gi = 0; gi < 3; gi++)
#pragma unroll
        for (int k = 0; k < 4; k++) {
            float v = racc[gi][k];
            v += __shfl_xor_sync(0xffffffffu, v, 1);
            v += __shfl_xor_sync(0xffffffffu, v, 2);
            v += __shfl_xor_sync(0xffffffffu, v, 4);
            v += __shfl_xor_sync(0xffffffffu, v, 8);
            if (tx == 0) rowsum[gi * 64 + ty + 16 * k] += v;
        }
    __syncthreads();

    float z = rowsum[t];
#pragma unroll
    for (int q = 0; q < 16; q++) z += red[q * NA + t];
    rowsum[t] = 0.0f;   // reset own slot for next call (barrier-separated)
    return z;
}

__device__ __forceinline__ float warp_sum(float v) {
#pragma unroll
    for (int off = 16; off; off >>= 1)
        v += __shfl_xor_sync(0xffffffffu, v, off);
    return v;
}

__device__ __forceinline__ void warp_sum3(float& a, float& b, float& c) {
#pragma unroll
    for (int off = 16; off; off >>= 1) {
        a += __shfl_xor_sync(0xffffffffu, a, off);
        b += __shfl_xor_sync(0xffffffffu, b, off);
        c += __shfl_xor_sync(0xffffffffu, c, off);
    }
}

__device__ __forceinline__ float clipc(float z) {
    return fminf(fmaxf(z, -CMAX), CMAX);
}

// ---------------------------------------------------------------------------
// Kernel 2: per-batch solver, Q resident in shared memory. occ = 1 CTA/SM.
// ---------------------------------------------------------------------------
__global__ __launch_bounds__(256) void solver_kernel(float* __restrict__ out) {
    extern __shared__ float sdyn[];           // [Q: 40960][red: 4096]
    float* Qs  = sdyn;
    float* red = sdyn + 40960;
    __shared__ float ys[NA];
    __shared__ float ws[NA];
    __shared__ float vs[NA];
    __shared__ float rowsum[NA];
    __shared__ float scal[2];

    const int b  = blockIdx.x;
    const int t  = threadIdx.x;
    const int ty = t >> 4;
    const int tx = t & 15;

    // copy this batch's Q into smem (10 * 4096 floats = 160 KB)
    {
        const float4* src = (const float4*)(g_Qs + (size_t)b * 10 * 4096);
        float4* dst = (float4*)Qs;
        for (int i = t; i < 10240; i += 256) dst[i] = src[i];
    }
    ys[t] = 0.0625f;   // 1/sqrt(256)
    rowsum[t] = 0.0f;
    __syncthreads();

    // ---------------- power iteration for lambda_max ----------------
    for (int it = 0; it < PITERS; it++) {
        float z = symv(Qs, ys, red, rowsum, t, ty, tx);
        vs[t] = z;
        __syncthreads();
        if (t < 32) {
            float zr[8];
            float ss = 0.0f;
#pragma unroll
            for (int k = 0; k < 8; k++) { zr[k] = vs[t + 32 * k]; ss = fmaf(zr[k], zr[k], ss); }
            ss = warp_sum(ss);
            float inv = 1.0f / (sqrtf(ss) + 1e-12f);
#pragma unroll
            for (int k = 0; k < 8; k++) ys[t + 32 * k] = zr[k] * inv;
        }
        __syncthreads();
    }
    {
        float z = symv(Qs, ys, red, rowsum, t, ty, tx);
        vs[t] = z;
        __syncthreads();
        if (t < 32) {
            float ss = 0.0f;
#pragma unroll
            for (int k = 0; k < 8; k++) ss = fmaf(ys[t + 32 * k], vs[t + 32 * k], ss);
            ss = warp_sum(ss);
            if (t == 0) scal[0] = 1.0f / (2.0f * ss + 1e-12f);
        }
        __syncthreads();
    }
    const float step = scal[0];

    // ---------------- FISTA ----------------
    ws[t] = 1.0f / 256.0f;
    ys[t] = 1.0f / 256.0f;
    float tf = 1.0f;
    __syncthreads();

    for (int it = 0; it < NITERS; it++) {
        float z = symv(Qs, ys, red, rowsum, t, ty, tx);
        vs[t] = ys[t] - step * (2.0f * z);
        __syncthreads();

        // --- projection: 3-point quartile search on warp 0 ---
        if (t < 32) {
            float vr[8];
#pragma unroll
            for (int k = 0; k < 8; k++) vr[k] = vs[t + 32 * k];
            float mn = vr[0], mx = vr[0];
#pragma unroll
            for (int k = 1; k < 8; k++) { mn = fminf(mn, vr[k]); mx = fmaxf(mx, vr[k]); }
#pragma unroll
            for (int off = 16; off; off >>= 1) {
                mn = fminf(mn, __shfl_xor_sync(0xffffffffu, mn, off));
                mx = fmaxf(mx, __shfl_xor_sync(0xffffffffu, mx, off));
            }
            float lo = mn - CMAX;
            float hi = mx + CMAX;
            for (int r = 0; r < TRIROUNDS; r++) {
                float d  = hi - lo;
                float m1 = lo + 0.25f * d;
                float m2 = lo + 0.50f * d;
                float m3 = lo + 0.75f * d;
                float s1 = 0.0f, s2 = 0.0f, s3 = 0.0f;
#pragma unroll
                for (int k = 0; k < 8; k++) {
                    s1 += clipc(vr[k] - m1);
                    s2 += clipc(vr[k] - m2);
                    s3 += clipc(vr[k] - m3);
                }
                warp_sum3(s1, s2, s3);
                if (s2 > 1.0f) {
                    bool p3 = s3 > 1.0f;
                    lo = p3 ? m3 : m2;
                    hi = p3 ? hi : m3;
                } else {
                    bool p1 = s1 > 1.0f;
                    lo = p1 ? m1 : lo;
                    hi = p1 ? m2 : m1;
                }
            }
            float tau0 = 0.5f * (lo + hi);
            float sv = 0.0f, cnt = 0.0f, dk = 0.0f;
#pragma unroll
            for (int k = 0; k < 8; k++) {
                float zz = vr[k] - tau0;
                bool in = fabsf(zz) < CMAX;
                if (in) { sv += vr[k]; cnt += 1.0f; }
                else    { dk += (zz >= CMAX) ? 1.0f : -1.0f; }
            }
            warp_sum3(sv, cnt, dk);
            float denom = fmaxf(cnt, 1.0f);
            float tau = (sv + CMAX * dk - 1.0f) / denom;
            if (t == 0) scal[1] = tau;
        }
        __syncthreads();

        // --- momentum update ---
        {
            float tau = scal[1];
            float wn = clipc(vs[t] - tau);
            float tn = 0.5f * (1.0f + sqrtf(1.0f + 4.0f * tf * tf));
            float yn = wn + ((tf - 1.0f) / tn) * (wn - ws[t]);
            ws[t] = wn;
            ys[t] = yn;
            tf = tn;
        }
        __syncthreads();
    }

    out[(size_t)b * NA + t] = ws[t];
}

// ---------------------------------------------------------------------------
extern "C" void kernel_launch(void* const* d_in, const int* in_sizes, int n_in,
                              void* d_out, int out_size) {
    (void)in_sizes; (void)n_in; (void)out_size;
    const float* A = (const float*)d_in[0];
    float* out = (float*)d_out;

    const int dyn_smem = (40960 + 16 * NA) * sizeof(float);   // 180224 B
    cudaFuncSetAttribute(solver_kernel,
                         cudaFuncAttributeMaxDynamicSharedMemorySize, dyn_smem);

    qbuild_kernel<<<dim3(10, 1, NB), 256>>>(A);
    solver_kernel<<<NB, 256, dyn_smem>>>(out);
}

// round 7
// speedup vs baseline: 1.7232x; 1.0406x over previous
#include <cuda_runtime.h>

#define NA 256
#define NB 512
#define CMAX 0.05f
#define NITERS 300
#define PITERS 30
#define QUADROUNDS 3
#define NEWTONROUNDS 6

// Upper-triangular Q blocks, fp32: 512 batches * 10 blocks * 64*64 floats = 82 MB
__device__ float g_Qs[(size_t)NB * 10 * 4096];

__constant__ int c_gi[10] = {0,0,0,0,1,1,1,2,2,3};
__constant__ int c_gj[10] = {0,1,2,3,1,2,3,2,3,3};

// ---------------------------------------------------------------------------
// Kernel 1: batched Q = A^T A, upper-triangular 64x64 tiles only.
// Grid (10,1,512), 256 threads. C[i][j] = sum_k A[k][i]*A[k][j]
// ---------------------------------------------------------------------------
__global__ __launch_bounds__(256) void qbuild_kernel(const float* __restrict__ A) {
    __shared__ float As[32][64];
    __shared__ float Bs[32][64];
    const int blk = blockIdx.x;
    const int b   = blockIdx.z;
    const int i0  = c_gi[blk] * 64;
    const int j0  = c_gj[blk] * 64;
    const float* Ab = A + (size_t)b * NA * NA;
    float*       Qb = g_Qs + ((size_t)b * 10 + blk) * 4096;
    const int t  = threadIdx.x;
    const int ty = t >> 4;
    const int tx = t & 15;

    float acc[4][4];
#pragma unroll
    for (int r = 0; r < 4; r++)
#pragma unroll
        for (int s = 0; s < 4; s++) acc[r][s] = 0.0f;

    for (int k0 = 0; k0 < NA; k0 += 32) {
        __syncthreads();
#pragma unroll
        for (int r = 0; r < 8; r++) {
            int idx = t + 256 * r;
            int kk = idx >> 6, c = idx & 63;
            As[kk][c] = Ab[(size_t)(k0 + kk) * NA + i0 + c];
            Bs[kk][c] = Ab[(size_t)(k0 + kk) * NA + j0 + c];
        }
        __syncthreads();
#pragma unroll
        for (int kk = 0; kk < 32; kk++) {
            float4 a4 = *(const float4*)&As[kk][ty * 4];
            float4 b4 = *(const float4*)&Bs[kk][tx * 4];
            float av[4] = {a4.x, a4.y, a4.z, a4.w};
            float bv[4] = {b4.x, b4.y, b4.z, b4.w};
#pragma unroll
            for (int r = 0; r < 4; r++)
#pragma unroll
                for (int s = 0; s < 4; s++)
                    acc[r][s] = fmaf(av[r], bv[s], acc[r][s]);
        }
    }
#pragma unroll
    for (int r = 0; r < 4; r++) {
        float4 o = make_float4(acc[r][0], acc[r][1], acc[r][2], acc[r][3]);
        *(float4*)&Qb[(ty * 4 + r) * 64 + tx * 4] = o;
    }
}

// ---------------------------------------------------------------------------
// Symmetric matvec from SMEM-resident upper-tri Q, 512 threads.
// Thread (ty=t>>4 in 0..31, tx=t&15): per block handles rows {ty, ty+32},
// columns 4tx..4tx+3.  Returns z[t]=(Qy)[t] for t<256 (else 0).
// ---------------------------------------------------------------------------
__device__ __forceinline__ float symv(const float* __restrict__ Qb,
                                      const float* __restrict__ y,
                                      float* __restrict__ red,
                                      float* __restrict__ rowsum,
                                      int t, int ty, int tx) {
    constexpr int GI[10] = {0,0,0,0,1,1,1,2,2,3};
    constexpr int GJ[10] = {0,1,2,3,1,2,3,2,3,3};
    float cacc[4][4];
    float racc[3][2];
#pragma unroll
    for (int s = 0; s < 4; s++)
#pragma unroll
        for (int c = 0; c < 4; c++) cacc[s][c] = 0.0f;
#pragma unroll
    for (int s = 0; s < 3; s++)
#pragma unroll
        for (int k = 0; k < 2; k++) racc[s][k] = 0.0f;

#pragma unroll
    for (int blk = 0; blk < 10; blk++) {
        const int gi = GI[blk];
        const int gj = GJ[blk];
        const float4* B4 = (const float4*)(Qb + blk * 4096);
        float4 yj = ((const float4*)(y + gj * 64))[tx];
#pragma unroll
        for (int k = 0; k < 2; k++) {
            int r = ty + 32 * k;
            float4 q = B4[r * 16 + tx];
            float yi = y[gi * 64 + r];
            cacc[gj][0] = fmaf(q.x, yi, cacc[gj][0]);
            cacc[gj][1] = fmaf(q.y, yi, cacc[gj][1]);
            cacc[gj][2] = fmaf(q.z, yi, cacc[gj][2]);
            cacc[gj][3] = fmaf(q.w, yi, cacc[gj][3]);
            if (gi != gj) {
                float d = q.x * yj.x;
                d = fmaf(q.y, yj.y, d);
                d = fmaf(q.z, yj.z, d);
                d = fmaf(q.w, yj.w, d);
                racc[gi][k] += d;
            }
        }
    }

    // column partials -> red[ty][seg*64 + col]   (32 rows of NA)
#pragma unroll
    for (int s = 0; s < 4; s++)
        ((float4*)(red + ty * NA + s * 64))[tx] =
            make_float4(cacc[s][0], cacc[s][1], cacc[s][2], cacc[s][3]);

    // row partials: reduce across the 16 tx lanes (half-warp)
#pragma unroll
    for (int gi = 0; gi < 3; gi++)
#pragma unroll
        for (int k = 0; k < 2; k++) {
            float v = racc[gi][k];
            v += __shfl_xor_sync(0xffffffffu, v, 1);
            v += __shfl_xor_sync(0xffffffffu, v, 2);
            v += __shfl_xor_sync(0xffffffffu, v, 4);
            v += __shfl_xor_sync(0xffffffffu, v, 8);
            if (tx == 0) rowsum[gi * 64 + ty + 32 * k] += v;
        }
    __syncthreads();

    float z = 0.0f;
    if (t < NA) {
        z = rowsum[t];
#pragma unroll
        for (int q = 0; q < 32; q++) z += red[q * NA + t];
        rowsum[t] = 0.0f;   // reset own slot; caller barriers before next symv
    }
    return z;
}

__device__ __forceinline__ float warp_sum(float v) {
#pragma unroll
    for (int off = 16; off; off >>= 1)
        v += __shfl_xor_sync(0xffffffffu, v, off);
    return v;
}

__device__ __forceinline__ void warp_sum2(float& a, float& b) {
#pragma unroll
    for (int off = 16; off; off >>= 1) {
        a += __shfl_xor_sync(0xffffffffu, a, off);
        b += __shfl_xor_sync(0xffffffffu, b, off);
    }
}

__device__ __forceinline__ void warp_sum3(float& a, float& b, float& c) {
#pragma unroll
    for (int off = 16; off; off >>= 1) {
        a += __shfl_xor_sync(0xffffffffu, a, off);
        b += __shfl_xor_sync(0xffffffffu, b, off);
        c += __shfl_xor_sync(0xffffffffu, c, off);
    }
}

__device__ __forceinline__ float clipc(float z) {
    return fminf(fmaxf(z, -CMAX), CMAX);
}

// ---------------------------------------------------------------------------
// Kernel 2: per-batch solver, Q in smem, 512 threads (16 warps). 1 CTA/SM.
// ---------------------------------------------------------------------------
__global__ __launch_bounds__(512) void solver_kernel(float* __restrict__ out) {
    extern __shared__ float sdyn[];           // [Q: 40960][red: 8192]
    float* Qs  = sdyn;
    float* red = sdyn + 40960;
    __shared__ float ys[NA];
    __shared__ float ws[NA];
    __shared__ float vs[NA];
    __shared__ float rowsum[NA];
    __shared__ float scal[2];

    const int b  = blockIdx.x;
    const int t  = threadIdx.x;
    const int ty = t >> 4;
    const int tx = t & 15;

    // copy this batch's Q into smem (10 * 4096 floats = 160 KB)
    {
        const float4* src = (const float4*)(g_Qs + (size_t)b * 10 * 4096);
        float4* dst = (float4*)Qs;
        for (int i = t; i < 10240; i += 512) dst[i] = src[i];
    }
    if (t < NA) { ys[t] = 0.0625f; rowsum[t] = 0.0f; }
    __syncthreads();

    // ---------------- power iteration for lambda_max ----------------
    for (int it = 0; it < PITERS; it++) {
        float z = symv(Qs, ys, red, rowsum, t, ty, tx);
        if (t < NA) vs[t] = z;
        __syncthreads();
        if (t < 32) {
            float zr[8];
            float ss = 0.0f;
#pragma unroll
            for (int k = 0; k < 8; k++) { zr[k] = vs[t + 32 * k]; ss = fmaf(zr[k], zr[k], ss); }
            ss = warp_sum(ss);
            float inv = 1.0f / (sqrtf(ss) + 1e-12f);
#pragma unroll
            for (int k = 0; k < 8; k++) ys[t + 32 * k] = zr[k] * inv;
        }
        __syncthreads();
    }
    {
        float z = symv(Qs, ys, red, rowsum, t, ty, tx);
        if (t < NA) vs[t] = z;
        __syncthreads();
        if (t < 32) {
            float ss = 0.0f;
#pragma unroll
            for (int k = 0; k < 8; k++) ss = fmaf(ys[t + 32 * k], vs[t + 32 * k], ss);
            ss = warp_sum(ss);
            if (t == 0) scal[0] = 1.0f / (2.0f * ss + 1e-12f);
        }
        __syncthreads();
    }
    const float step = scal[0];

    // ---------------- FISTA ----------------
    if (t < NA) { ws[t] = 1.0f / 256.0f; ys[t] = 1.0f / 256.0f; }
    float tf = 1.0f;
    __syncthreads();

    for (int it = 0; it < NITERS; it++) {
        float z = symv(Qs, ys, red, rowsum, t, ty, tx);
        if (t < NA) vs[t] = ys[t] - step * (2.0f * z);
        __syncthreads();

        // --- projection on warp 0: quartile bracket + safeguarded Newton ---
        if (t < 32) {
            float vr[8];
#pragma unroll
            for (int k = 0; k < 8; k++) vr[k] = vs[t + 32 * k];
            float mn = vr[0], mx = vr[0];
#pragma unroll
            for (int k = 1; k < 8; k++) { mn = fminf(mn, vr[k]); mx = fmaxf(mx, vr[k]); }
#pragma unroll
            for (int off = 16; off; off >>= 1) {
                mn = fminf(mn, __shfl_xor_sync(0xffffffffu, mn, off));
                mx = fmaxf(mx, __shfl_xor_sync(0xffffffffu, mx, off));
            }
            float lo = mn - CMAX;
            float hi = mx + CMAX;
            for (int r = 0; r < QUADROUNDS; r++) {
                float d  = hi - lo;
                float m1 = lo + 0.25f * d;
                float m2 = lo + 0.50f * d;
                float m3 = lo + 0.75f * d;
                float s1 = 0.0f, s2 = 0.0f, s3 = 0.0f;
#pragma unroll
                for (int k = 0; k < 8; k++) {
                    s1 += clipc(vr[k] - m1);
                    s2 += clipc(vr[k] - m2);
                    s3 += clipc(vr[k] - m3);
                }
                warp_sum3(s1, s2, s3);
                if (s2 > 1.0f) {
                    bool p3 = s3 > 1.0f;
                    lo = p3 ? m3 : m2;
                    hi = p3 ? hi : m3;
                } else {
                    bool p1 = s1 > 1.0f;
                    lo = p1 ? m1 : lo;
                    hi = p1 ? m2 : m1;
                }
            }
            float tau0 = 0.5f * (lo + hi);
            // safeguarded Newton on s(tau) (pw-linear, slope = -cnt)
            for (int r = 0; r < NEWTONROUNDS; r++) {
                float s = 0.0f, cnt = 0.0f;
#pragma unroll
                for (int k = 0; k < 8; k++) {
                    float zz = vr[k] - tau0;
                    s += clipc(zz);
                    cnt += (fabsf(zz) < CMAX) ? 1.0f : 0.0f;
                }
                warp_sum2(s, cnt);
                bool p = s > 1.0f;
                lo = p ? tau0 : lo;
                hi = p ? hi : tau0;
                float nt = tau0 + (s - 1.0f) / fmaxf(cnt, 1.0f);
                tau0 = (nt > lo && nt < hi) ? nt : 0.5f * (lo + hi);
            }
            // exact tau from active set (matches reference recompute)
            float sv = 0.0f, cnt = 0.0f, dk = 0.0f;
#pragma unroll
            for (int k = 0; k < 8; k++) {
                float zz = vr[k] - tau0;
                bool in = fabsf(zz) < CMAX;
                if (in) { sv += vr[k]; cnt += 1.0f; }
                else    { dk += (zz >= CMAX) ? 1.0f : -1.0f; }
            }
            warp_sum3(sv, cnt, dk);
            float denom = fmaxf(cnt, 1.0f);
            float tau = (sv + CMAX * dk - 1.0f) / denom;
            if (t == 0) scal[1] = tau;
        }
        __syncthreads();

        // --- momentum update ---
        if (t < NA) {
            float tau = scal[1];
            float wn = clipc(vs[t] - tau);
            float tn = 0.5f * (1.0f + sqrtf(1.0f + 4.0f * tf * tf));
            float yn = wn + ((tf - 1.0f) / tn) * (wn - ws[t]);
            ws[t] = wn;
            ys[t] = yn;
            tf = tn;
        } else {
            float tn = 0.5f * (1.0f + sqrtf(1.0f + 4.0f * tf * tf));
            tf = tn;
        }
        __syncthreads();
    }

    if (t < NA) out[(size_t)b * NA + t] = ws[t];
}

// ---------------------------------------------------------------------------
extern "C" void kernel_launch(void* const* d_in, const int* in_sizes, int n_in,
                              void* d_out, int out_size) {
    (void)in_sizes; (void)n_in; (void)out_size;
    const float* A = (const float*)d_in[0];
    float* out = (float*)d_out;

    const int dyn_smem = (40960 + 32 * NA) * sizeof(float);   // 196608 B
    cudaFuncSetAttribute(solver_kernel,
                         cudaFuncAttributeMaxDynamicSharedMemorySize, dyn_smem);

    qbuild_kernel<<<dim3(10, 1, NB), 256>>>(A);
    solver_kernel<<<NB, 512, dyn_smem>>>(out);
}

// round 9
// speedup vs baseline: 1.9446x; 1.1285x over previous
#include <cuda_runtime.h>

#define NA 256
#define NB 512
#define CMAX 0.05f
#define NITERS 300
#define PITERS 30
#define QUADROUNDS 3
#define NEWTONROUNDS 6

// Upper-triangular Q blocks, fp32: 512 batches * 10 blocks * 64*64 floats = 82 MB
__device__ float g_Qs[(size_t)NB * 10 * 4096];

__constant__ int c_gi[10] = {0,0,0,0,1,1,1,2,2,3};
__constant__ int c_gj[10] = {0,1,2,3,1,2,3,2,3,3};

// ---------------------------------------------------------------------------
// Kernel 1: batched Q = A^T A, upper-triangular 64x64 tiles only.
// ---------------------------------------------------------------------------
__global__ __launch_bounds__(256) void qbuild_kernel(const float* __restrict__ A) {
    __shared__ float As[32][64];
    __shared__ float Bs[32][64];
    const int blk = blockIdx.x;
    const int b   = blockIdx.z;
    const int i0  = c_gi[blk] * 64;
    const int j0  = c_gj[blk] * 64;
    const float* Ab = A + (size_t)b * NA * NA;
    float*       Qb = g_Qs + ((size_t)b * 10 + blk) * 4096;
    const int t  = threadIdx.x;
    const int ty = t >> 4;
    const int tx = t & 15;

    float acc[4][4];
#pragma unroll
    for (int r = 0; r < 4; r++)
#pragma unroll
        for (int s = 0; s < 4; s++) acc[r][s] = 0.0f;

    for (int k0 = 0; k0 < NA; k0 += 32) {
        __syncthreads();
#pragma unroll
        for (int r = 0; r < 8; r++) {
            int idx = t + 256 * r;
            int kk = idx >> 6, c = idx & 63;
            As[kk][c] = Ab[(size_t)(k0 + kk) * NA + i0 + c];
            Bs[kk][c] = Ab[(size_t)(k0 + kk) * NA + j0 + c];
        }
        __syncthreads();
#pragma unroll
        for (int kk = 0; kk < 32; kk++) {
            float4 a4 = *(const float4*)&As[kk][ty * 4];
            float4 b4 = *(const float4*)&Bs[kk][tx * 4];
            float av[4] = {a4.x, a4.y, a4.z, a4.w};
            float bv[4] = {b4.x, b4.y, b4.z, b4.w};
#pragma unroll
            for (int r = 0; r < 4; r++)
#pragma unroll
                for (int s = 0; s < 4; s++)
                    acc[r][s] = fmaf(av[r], bv[s], acc[r][s]);
        }
    }
#pragma unroll
    for (int r = 0; r < 4; r++) {
        float4 o = make_float4(acc[r][0], acc[r][1], acc[r][2], acc[r][3]);
        *(float4*)&Qb[(ty * 4 + r) * 64 + tx * 4] = o;
    }
}

__device__ __forceinline__ float warp_sum(float v) {
#pragma unroll
    for (int off = 16; off; off >>= 1)
        v += __shfl_xor_sync(0xffffffffu, v, off);
    return v;
}

__device__ __forceinline__ void warp_sum2(float& a, float& b) {
#pragma unroll
    for (int off = 16; off; off >>= 1) {
        a += __shfl_xor_sync(0xffffffffu, a, off);
        b += __shfl_xor_sync(0xffffffffu, b, off);
    }
}

__device__ __forceinline__ void warp_sum3(float& a, float& b, float& c) {
#pragma unroll
    for (int off = 16; off; off >>= 1) {
        a += __shfl_xor_sync(0xffffffffu, a, off);
        b += __shfl_xor_sync(0xffffffffu, b, off);
        c += __shfl_xor_sync(0xffffffffu, c, off);
    }
}

__device__ __forceinline__ float clipc(float z) {
    return fminf(fmaxf(z, -CMAX), CMAX);
}

// ---------------------------------------------------------------------------
// Kernel 2: per-batch solver, Q REGISTER-RESIDENT. 512 threads, 1 CTA/SM.
// Thread (ty=t>>4 in 0..31, tx=t&15) owns, for each of the 10 blocks, rows
// {ty, ty+32} x cols 4tx..4tx+3  ->  10*2*4 = 80 floats of Q in registers.
// ---------------------------------------------------------------------------
__global__ __launch_bounds__(512) void solver_kernel(float* __restrict__ out) {
    extern __shared__ float sdyn[];           // red[32*256]
    float* red = sdyn;
    __shared__ float ys[NA];
    __shared__ float ws[NA];
    __shared__ float vs[NA];
    __shared__ float rowsum[NA];
    __shared__ float scal[2];

    const int b  = blockIdx.x;
    const int t  = threadIdx.x;
    const int ty = t >> 4;
    const int tx = t & 15;

    constexpr int GI[10] = {0,0,0,0,1,1,1,2,2,3};
    constexpr int GJ[10] = {0,1,2,3,1,2,3,2,3,3};

    // ---- load this thread's 80-float Q slice into registers ----
    float qv[20][4];
    {
        const float4* Qb4 = (const float4*)(g_Qs + (size_t)b * 10 * 4096);
#pragma unroll
        for (int blk = 0; blk < 10; blk++)
#pragma unroll
            for (int k = 0; k < 2; k++) {
                float4 q = Qb4[blk * 1024 + (ty + 32 * k) * 16 + tx];
                qv[blk * 2 + k][0] = q.x;
                qv[blk * 2 + k][1] = q.y;
                qv[blk * 2 + k][2] = q.z;
                qv[blk * 2 + k][3] = q.w;
            }
    }
    if (t < NA) { ys[t] = 0.0625f; rowsum[t] = 0.0f; }
    __syncthreads();

    // ---- symv as a lambda over register Q; returns z[t]=(Qy)[t] for t<256 ----
    auto symv = [&]() -> float {
        float cacc[4][4];
        float racc[3][2];
#pragma unroll
        for (int s = 0; s < 4; s++)
#pragma unroll
            for (int c = 0; c < 4; c++) cacc[s][c] = 0.0f;
#pragma unroll
        for (int s = 0; s < 3; s++)
#pragma unroll
            for (int k = 0; k < 2; k++) racc[s][k] = 0.0f;

#pragma unroll
        for (int blk = 0; blk < 10; blk++) {
            const int gi = GI[blk];
            const int gj = GJ[blk];
            float4 yj = ((const float4*)(ys + gj * 64))[tx];
#pragma unroll
            for (int k = 0; k < 2; k++) {
                const float* q = qv[blk * 2 + k];
                float yi = ys[gi * 64 + ty + 32 * k];
                cacc[gj][0] = fmaf(q[0], yi, cacc[gj][0]);
                cacc[gj][1] = fmaf(q[1], yi, cacc[gj][1]);
                cacc[gj][2] = fmaf(q[2], yi, cacc[gj][2]);
                cacc[gj][3] = fmaf(q[3], yi, cacc[gj][3]);
                if (gi != gj) {
                    float d = q[0] * yj.x;
                    d = fmaf(q[1], yj.y, d);
                    d = fmaf(q[2], yj.z, d);
                    d = fmaf(q[3], yj.w, d);
                    racc[gi][k] += d;
                }
            }
        }

        // column partials -> red[ty][seg*64 + col]
#pragma unroll
        for (int s = 0; s < 4; s++)
            ((float4*)(red + ty * NA + s * 64))[tx] =
                make_float4(cacc[s][0], cacc[s][1], cacc[s][2], cacc[s][3]);

        // row partials: reduce across 16 tx lanes (half-warp)
#pragma unroll
        for (int gi = 0; gi < 3; gi++)
#pragma unroll
            for (int k = 0; k < 2; k++) {
                float v = racc[gi][k];
                v += __shfl_xor_sync(0xffffffffu, v, 1);
                v += __shfl_xor_sync(0xffffffffu, v, 2);
                v += __shfl_xor_sync(0xffffffffu, v, 4);
                v += __shfl_xor_sync(0xffffffffu, v, 8);
                if (tx == 0) rowsum[gi * 64 + ty + 32 * k] += v;
            }
        __syncthreads();

        float z = 0.0f;
        if (t < NA) {
            z = rowsum[t];
#pragma unroll
            for (int q = 0; q < 32; q++) z += red[q * NA + t];
            rowsum[t] = 0.0f;   // reset own slot; barrier before next symv
        }
        return z;
    };

    // ---------------- power iteration for lambda_max ----------------
    for (int it = 0; it < PITERS; it++) {
        float z = symv();
        if (t < NA) vs[t] = z;
        __syncthreads();
        if (t < 32) {
            float zr[8];
            float ss = 0.0f;
#pragma unroll
            for (int k = 0; k < 8; k++) { zr[k] = vs[t + 32 * k]; ss = fmaf(zr[k], zr[k], ss); }
            ss = warp_sum(ss);
            float inv = 1.0f / (sqrtf(ss) + 1e-12f);
#pragma unroll
            for (int k = 0; k < 8; k++) ys[t + 32 * k] = zr[k] * inv;
        }
        __syncthreads();
    }
    {
        float z = symv();
        if (t < NA) vs[t] = z;
        __syncthreads();
        if (t < 32) {
            float ss = 0.0f;
#pragma unroll
            for (int k = 0; k < 8; k++) ss = fmaf(ys[t + 32 * k], vs[t + 32 * k], ss);
            ss = warp_sum(ss);
            if (t == 0) scal[0] = 1.0f / (2.0f * ss + 1e-12f);
        }
        __syncthreads();
    }
    const float step = scal[0];

    // ---------------- FISTA ----------------
    if (t < NA) { ws[t] = 1.0f / 256.0f; ys[t] = 1.0f / 256.0f; }
    float tf = 1.0f;
    __syncthreads();

    for (int it = 0; it < NITERS; it++) {
        float z = symv();
        if (t < NA) vs[t] = ys[t] - step * (2.0f * z);
        __syncthreads();

        // --- projection on warp 0: quartile bracket + safeguarded Newton ---
        if (t < 32) {
            float vr[8];
#pragma unroll
            for (int k = 0; k < 8; k++) vr[k] = vs[t + 32 * k];
            float mn = vr[0], mx = vr[0];
#pragma unroll
            for (int k = 1; k < 8; k++) { mn = fminf(mn, vr[k]); mx = fmaxf(mx, vr[k]); }
#pragma unroll
            for (int off = 16; off; off >>= 1) {
                mn = fminf(mn, __shfl_xor_sync(0xffffffffu, mn, off));
                mx = fmaxf(mx, __shfl_xor_sync(0xffffffffu, mx, off));
            }
            float lo = mn - CMAX;
            float hi = mx + CMAX;
            for (int r = 0; r < QUADROUNDS; r++) {
                float d  = hi - lo;
                float m1 = lo + 0.25f * d;
                float m2 = lo + 0.50f * d;
                float m3 = lo + 0.75f * d;
                float s1 = 0.0f, s2 = 0.0f, s3 = 0.0f;
#pragma unroll
                for (int k = 0; k < 8; k++) {
                    s1 += clipc(vr[k] - m1);
                    s2 += clipc(vr[k] - m2);
                    s3 += clipc(vr[k] - m3);
                }
                warp_sum3(s1, s2, s3);
                if (s2 > 1.0f) {
                    bool p3 = s3 > 1.0f;
                    lo = p3 ? m3 : m2;
                    hi = p3 ? hi : m3;
                } else {
                    bool p1 = s1 > 1.0f;
                    lo = p1 ? m1 : lo;
                    hi = p1 ? m2 : m1;
                }
            }
            float tau0 = 0.5f * (lo + hi);
            for (int r = 0; r < NEWTONROUNDS; r++) {
                float s = 0.0f, cnt = 0.0f;
#pragma unroll
                for (int k = 0; k < 8; k++) {
                    float zz = vr[k] - tau0;
                    s += clipc(zz);
                    cnt += (fabsf(zz) < CMAX) ? 1.0f : 0.0f;
                }
                warp_sum2(s, cnt);
                bool p = s > 1.0f;
                lo = p ? tau0 : lo;
                hi = p ? hi : tau0;
                float nt = tau0 + (s - 1.0f) / fmaxf(cnt, 1.0f);
                tau0 = (nt > lo && nt < hi) ? nt : 0.5f * (lo + hi);
            }
            // exact tau from active set (matches reference recompute)
            float sv = 0.0f, cnt = 0.0f, dk = 0.0f;
#pragma unroll
            for (int k = 0; k < 8; k++) {
                float zz = vr[k] - tau0;
                bool in = fabsf(zz) < CMAX;
                if (in) { sv += vr[k]; cnt += 1.0f; }
                else    { dk += (zz >= CMAX) ? 1.0f : -1.0f; }
            }
            warp_sum3(sv, cnt, dk);
            float denom = fmaxf(cnt, 1.0f);
            float tau = (sv + CMAX * dk - 1.0f) / denom;
            if (t == 0) scal[1] = tau;
        }
        __syncthreads();

        // --- momentum update ---
        {
            float tn = 0.5f * (1.0f + sqrtf(1.0f + 4.0f * tf * tf));
            if (t < NA) {
                float tau = scal[1];
                float wn = clipc(vs[t] - tau);
                float yn = wn + ((tf - 1.0f) / tn) * (wn - ws[t]);
                ws[t] = wn;
                ys[t] = yn;
            }
            tf = tn;
        }
        __syncthreads();
    }

    if (t < NA) out[(size_t)b * NA + t] = ws[t];
}

// ---------------------------------------------------------------------------
extern "C" void kernel_launch(void* const* d_in, const int* in_sizes, int n_in,
                              void* d_out, int out_size) {
    (void)in_sizes; (void)n_in; (void)out_size;
    const float* A = (const float*)d_in[0];
    float* out = (float*)d_out;

    const int dyn_smem = (32 * NA) * sizeof(float);   // 32 KB
    cudaFuncSetAttribute(solver_kernel,
                         cudaFuncAttributeMaxDynamicSharedMemorySize, dyn_smem);

    qbuild_kernel<<<dim3(10, 1, NB), 256>>>(A);
    solver_kernel<<<NB, 512, dyn_smem>>>(out);
}